// round 7
// baseline (speedup 1.0000x reference)
#include <cuda_runtime.h>
#include <math.h>

// ---------------------------------------------------------------------------
// MinkNeXtBlock: x -> 1x1conv -> LN+GELU -> sparse_conv3(W1) -> LN+GELU
//                  -> sparse_conv3(W2) -> LN -> +x -> GELU
// N=100000 rows, Cin=32, Cmid=128, K=27 neighbor offsets.
// ---------------------------------------------------------------------------

#define NMAX 100000
#define KK   27

// Scratch (device globals: no allocation allowed in kernel_launch)
__device__ float g_h0[NMAX * 32];    // after conv0+LN+GELU      (12.8 MB)
__device__ float g_h1[NMAX * 128];   // after conv1+LN+GELU      (51.2 MB)
__device__ int   g_mask_w4;          // 1 if mask stored as int32, 0 if 1-byte

// ---------------------------------------------------------------------------

__device__ __forceinline__ float gelu_f(float v) {
    // exact (erf) gelu, matching jax.nn.gelu(approximate=False)
    return 0.5f * v * (1.0f + erff(v * 0.70710678118654752f));
}

__device__ __forceinline__ unsigned long long splat2(float x) {
    unsigned long long r; unsigned int u = __float_as_uint(x);
    asm("mov.b64 %0, {%1, %1};" : "=l"(r) : "r"(u));
    return r;
}
__device__ __forceinline__ void fma2(unsigned long long& d,
                                     unsigned long long a, unsigned long long b) {
    asm("fma.rn.f32x2 %0, %1, %2, %0;" : "+l"(d) : "l"(a), "l"(b));
}
__device__ __forceinline__ float2 unpk(unsigned long long v) {
    unsigned int lo, hi;
    asm("mov.b64 {%0, %1}, %2;" : "=r"(lo), "=r"(hi) : "l"(v));
    return make_float2(__uint_as_float(lo), __uint_as_float(hi));
}

// Read mask element robustly (byte layout or int32 layout, detected at runtime)
__device__ __forceinline__ int mask_at(const void* m, int off, int w4) {
    if (w4) return ((const int*)m)[off];
    return (int)((const unsigned char*)m)[off];
}

// ---------------------------------------------------------------------------
// Kernel 0: h0 = gelu(LN(x @ Wc)); one warp per row. Also detects mask layout.
// ---------------------------------------------------------------------------
__global__ void k_conv0(const float* __restrict__ x, const float* __restrict__ Wc,
                        const float* __restrict__ g0, const float* __restrict__ b0,
                        const unsigned char* __restrict__ maskraw, int n) {
    __shared__ float sW[32 * 32];
    int tid = threadIdx.x;
    if (blockIdx.x == 0 && tid == 0) {
        // If mask is int32 (values 0/1, little-endian), all bytes at offsets
        // not divisible by 4 are zero. If it is 1-byte bool, ~half of the
        // first few hundred bytes are 1 (prob of false negative ~2^-150).
        int w4 = 1;
        for (int t = 1; t < 400; ++t) {
            if ((t & 3) != 0 && maskraw[t] != 0) { w4 = 0; break; }
        }
        g_mask_w4 = w4;
    }
    for (int i = tid; i < 1024; i += 256) sW[i] = Wc[i];
    __syncthreads();

    int lane = tid & 31, w = tid >> 5;
    int row = blockIdx.x * 8 + w;
    if (row >= n) return;

    float xv = x[row * 32 + lane];
    float acc = 0.0f;
#pragma unroll
    for (int c = 0; c < 32; ++c) {
        float xs = __shfl_sync(0xffffffffu, xv, c);
        acc = fmaf(xs, sW[c * 32 + lane], acc);
    }
    // LayerNorm over 32 channels (one per lane)
    float s = acc;
#pragma unroll
    for (int o = 16; o > 0; o >>= 1) s += __shfl_xor_sync(0xffffffffu, s, o);
    float mu = s * (1.0f / 32.0f);
    float d = acc - mu;
    float q = d * d;
#pragma unroll
    for (int o = 16; o > 0; o >>= 1) q += __shfl_xor_sync(0xffffffffu, q, o);
    float var = q * (1.0f / 32.0f);
    float y = d * rsqrtf(var + 1e-6f) * g0[lane] + b0[lane];
    g_h0[row * 32 + lane] = gelu_f(y);
}

// ---------------------------------------------------------------------------
// Kernel 1: h1 = gelu(LN(sparse_conv3(h0, W1)))    Cin=32 -> Cout=128
// 128-row tiles, 256 threads, 8x8 outputs/thread, fma.rn.f32x2 inner loop.
// ---------------------------------------------------------------------------
__global__ void __launch_bounds__(256, 2)
k_conv1(const float* __restrict__ W1, const int* __restrict__ nidx,
        const void* __restrict__ nmask,
        const float* __restrict__ g1, const float* __restrict__ b1, int n) {
    __shared__ union {
        struct { float A[32][128]; float W[32][128]; } s;  // 32 KB
        float red[2][128][17];                              // 17.4 KB (epilogue)
    } u;
    __shared__ int sidx[KK * 128];   // masked neighbor index, -1 = skip

    int tid = threadIdx.x;
    int row0 = blockIdx.x * 128;
    int w4 = g_mask_w4;

    for (int t = tid; t < KK * 128; t += 256) {
        int m = t / KK, k = t % KK;
        int nr = row0 + m;
        int id = -1;
        if (nr < n) {
            int off = nr * KK + k;
            if (mask_at(nmask, off, w4)) id = nidx[off];
        }
        sidx[k * 128 + m] = id;
    }

    int ty = tid >> 4, tx = tid & 15;         // rows ty*8.., cols tx*8..
    float gg[8], bb[8];
#pragma unroll
    for (int j = 0; j < 8; ++j) { gg[j] = g1[tx * 8 + j]; bb[j] = b1[tx * 8 + j]; }

    unsigned long long acc[4][8];             // [row-pair][col], f32x2 packed
#pragma unroll
    for (int p = 0; p < 4; ++p)
#pragma unroll
        for (int j = 0; j < 8; ++j) acc[p][j] = 0ull;

    int gm = tid & 127, gcb = tid >> 7;       // gather: my row & base col-group

    for (int k = 0; k < KK; ++k) {
        __syncthreads();
        // stage W1[k]: 32x128 floats
        {
            const float4* src = (const float4*)(W1 + k * (32 * 128));
            float4* dst = (float4*)&u.s.W[0][0];
#pragma unroll
            for (int i = 0; i < 4; ++i) dst[tid + i * 256] = src[tid + i * 256];
        }
        // gather A (transposed: A[c][m]) with mask/zero fill
        {
            int id = sidx[k * 128 + gm];
            const float4* srow = (const float4*)(g_h0 + (id >= 0 ? id : 0) * 32);
#pragma unroll
            for (int i = 0; i < 4; ++i) {
                int cg = gcb + 2 * i;         // 0..7
                float4 v = make_float4(0.f, 0.f, 0.f, 0.f);
                if (id >= 0) v = srow[cg];
                u.s.A[cg * 4 + 0][gm] = v.x;
                u.s.A[cg * 4 + 1][gm] = v.y;
                u.s.A[cg * 4 + 2][gm] = v.z;
                u.s.A[cg * 4 + 3][gm] = v.w;
            }
        }
        __syncthreads();
#pragma unroll
        for (int c = 0; c < 32; ++c) {
            const ulonglong2* ap = (const ulonglong2*)&u.s.A[c][ty * 8];
            ulonglong2 A0 = ap[0], A1 = ap[1];
            unsigned long long apair[4] = { A0.x, A0.y, A1.x, A1.y };
            const float4* wp = (const float4*)&u.s.W[c][tx * 8];
            float4 w0 = wp[0], w1 = wp[1];
            float ws[8] = { w0.x, w0.y, w0.z, w0.w, w1.x, w1.y, w1.z, w1.w };
#pragma unroll
            for (int j = 0; j < 8; ++j) {
                unsigned long long wsp = splat2(ws[j]);
#pragma unroll
                for (int p = 0; p < 4; ++p) fma2(acc[p][j], apair[p], wsp);
            }
        }
    }

    // unpack: row i = ty*8 + 2p + (lo/hi), col = tx*8 + j
    float vv[8][8];
#pragma unroll
    for (int p = 0; p < 4; ++p)
#pragma unroll
        for (int j = 0; j < 8; ++j) {
            float2 t = unpk(acc[p][j]);
            vv[2 * p][j] = t.x; vv[2 * p + 1][j] = t.y;
        }

    __syncthreads();   // everyone done reading A/W before red overwrites them
#pragma unroll
    for (int i = 0; i < 8; ++i) {
        float ps = 0.f, pq = 0.f;
#pragma unroll
        for (int j = 0; j < 8; ++j) { float v = vv[i][j]; ps += v; pq = fmaf(v, v, pq); }
        u.red[0][ty * 8 + i][tx] = ps;
        u.red[1][ty * 8 + i][tx] = pq;
    }
    __syncthreads();
#pragma unroll
    for (int i = 0; i < 8; ++i) {
        int r = ty * 8 + i;
        int nr = row0 + r;
        if (nr >= n) continue;
        float s = 0.f, q = 0.f;
#pragma unroll
        for (int t = 0; t < 16; ++t) { s += u.red[0][r][t]; q += u.red[1][r][t]; }
        float mu = s * (1.0f / 128.0f);
        float var = q * (1.0f / 128.0f) - mu * mu;
        float rs = rsqrtf(var + 1e-6f);
        float ov[8];
#pragma unroll
        for (int j = 0; j < 8; ++j) {
            float y = (vv[i][j] - mu) * rs * gg[j] + bb[j];
            ov[j] = gelu_f(y);
        }
        float4* dst = (float4*)(g_h1 + (size_t)nr * 128 + tx * 8);
        dst[0] = make_float4(ov[0], ov[1], ov[2], ov[3]);
        dst[1] = make_float4(ov[4], ov[5], ov[6], ov[7]);
    }
}

// ---------------------------------------------------------------------------
// Kernel 2: out = gelu(LN(sparse_conv3(h1, W2)) + x)    Cin=128 -> Cout=32
// 128-row tiles, 256 threads, 8x2 outputs/thread. Dynamic smem (~94 KB).
// ---------------------------------------------------------------------------
struct SmemC2 {
    union {
        float A[128][128];          // 64 KB   [c][m]
        float red[2][128][17];      // 17.4 KB (epilogue)
    };
    float W[128][32];               // 16 KB   [c][d]
    int   sidx[KK * 128];           // 13.5 KB
};

__global__ void __launch_bounds__(256, 2)
k_conv2(const float* __restrict__ x, const float* __restrict__ W2,
        const int* __restrict__ nidx, const void* __restrict__ nmask,
        const float* __restrict__ g2, const float* __restrict__ b2,
        float* __restrict__ out, int n) {
    extern __shared__ char dynsmem[];
    SmemC2& sm = *(SmemC2*)dynsmem;

    int tid = threadIdx.x;
    int row0 = blockIdx.x * 128;
    int w4 = g_mask_w4;

    for (int t = tid; t < KK * 128; t += 256) {
        int m = t / KK, k = t % KK;
        int nr = row0 + m;
        int id = -1;
        if (nr < n) {
            int off = nr * KK + k;
            if (mask_at(nmask, off, w4)) id = nidx[off];
        }
        sm.sidx[k * 128 + m] = id;
    }

    int ty = tid >> 4, tx = tid & 15;         // rows ty*8.., cols tx*2..
    float gg0 = g2[tx * 2], gg1 = g2[tx * 2 + 1];
    float bb0 = b2[tx * 2], bb1 = b2[tx * 2 + 1];

    unsigned long long acc[4][2];             // [row-pair][col]
#pragma unroll
    for (int p = 0; p < 4; ++p) { acc[p][0] = 0ull; acc[p][1] = 0ull; }

    int gm = tid & 127, gcb = tid >> 7;

    for (int k = 0; k < KK; ++k) {
        __syncthreads();
        // stage W2[k]: 128x32 floats
        {
            const float4* src = (const float4*)(W2 + k * (128 * 32));
            float4* dst = (float4*)&sm.W[0][0];
#pragma unroll
            for (int i = 0; i < 4; ++i) dst[tid + i * 256] = src[tid + i * 256];
        }
        // gather A[c][m]: each thread copies half of one 512B row
        {
            int id = sm.sidx[k * 128 + gm];
            const float4* srow = (const float4*)(g_h1 + (size_t)(id >= 0 ? id : 0) * 128);
#pragma unroll
            for (int i = 0; i < 16; ++i) {
                int cg = gcb + 2 * i;         // 0..31
                float4 v = make_float4(0.f, 0.f, 0.f, 0.f);
                if (id >= 0) v = srow[cg];
                sm.A[cg * 4 + 0][gm] = v.x;
                sm.A[cg * 4 + 1][gm] = v.y;
                sm.A[cg * 4 + 2][gm] = v.z;
                sm.A[cg * 4 + 3][gm] = v.w;
            }
        }
        __syncthreads();
#pragma unroll 8
        for (int c = 0; c < 128; ++c) {
            const ulonglong2* ap = (const ulonglong2*)&sm.A[c][ty * 8];
            ulonglong2 A0 = ap[0], A1 = ap[1];
            unsigned long long apair[4] = { A0.x, A0.y, A1.x, A1.y };
            float2 w = *(const float2*)&sm.W[c][tx * 2];
            unsigned long long ws0 = splat2(w.x), ws1 = splat2(w.y);
#pragma unroll
            for (int p = 0; p < 4; ++p) {
                fma2(acc[p][0], apair[p], ws0);
                fma2(acc[p][1], apair[p], ws1);
            }
        }
    }

    float vv[8][2];
#pragma unroll
    for (int p = 0; p < 4; ++p)
#pragma unroll
        for (int j = 0; j < 2; ++j) {
            float2 t = unpk(acc[p][j]);
            vv[2 * p][j] = t.x; vv[2 * p + 1][j] = t.y;
        }

    __syncthreads();
#pragma unroll
    for (int i = 0; i < 8; ++i) {
        float v0 = vv[i][0], v1 = vv[i][1];
        sm.red[0][ty * 8 + i][tx] = v0 + v1;
        sm.red[1][ty * 8 + i][tx] = v0 * v0 + v1 * v1;
    }
    __syncthreads();
#pragma unroll
    for (int i = 0; i < 8; ++i) {
        int r = ty * 8 + i;
        int nr = row0 + r;
        if (nr >= n) continue;
        float s = 0.f, q = 0.f;
#pragma unroll
        for (int t = 0; t < 16; ++t) { s += sm.red[0][r][t]; q += sm.red[1][r][t]; }
        float mu = s * (1.0f / 32.0f);
        float var = q * (1.0f / 32.0f) - mu * mu;
        float rs = rsqrtf(var + 1e-6f);
        float2 xres = *(const float2*)(x + nr * 32 + tx * 2);
        float y0 = (vv[i][0] - mu) * rs * gg0 + bb0 + xres.x;
        float y1 = (vv[i][1] - mu) * rs * gg1 + bb1 + xres.y;
        *(float2*)(out + nr * 32 + tx * 2) = make_float2(gelu_f(y0), gelu_f(y1));
    }
}

// ---------------------------------------------------------------------------

extern "C" void kernel_launch(void* const* d_in, const int* in_sizes, int n_in,
                              void* d_out, int out_size) {
    const float* x   = (const float*)d_in[0];
    const int*   nid = (const int*)d_in[1];
    const void*  msk = (const void*)d_in[2];
    const float* Wc  = (const float*)d_in[3];
    const float* g0  = (const float*)d_in[4];
    const float* b0  = (const float*)d_in[5];
    const float* W1  = (const float*)d_in[6];
    const float* g1  = (const float*)d_in[7];
    const float* b1  = (const float*)d_in[8];
    const float* W2  = (const float*)d_in[9];
    const float* g2  = (const float*)d_in[10];
    const float* b2  = (const float*)d_in[11];
    float* out = (float*)d_out;
    int n = in_sizes[0] / 32;

    cudaFuncSetAttribute(k_conv2, cudaFuncAttributeMaxDynamicSharedMemorySize,
                         (int)sizeof(SmemC2));

    k_conv0<<<(n + 7) / 8, 256>>>(x, Wc, g0, b0, (const unsigned char*)msk, n);
    int nb = (n + 127) / 128;
    k_conv1<<<nb, 256>>>(W1, nid, msk, g1, b1, n);
    k_conv2<<<nb, 256, sizeof(SmemC2)>>>(x, W2, nid, msk, g2, b2, out, n);
}

// round 9
// speedup vs baseline: 2.1102x; 2.1102x over previous
#include <cuda_runtime.h>
#include <math.h>
#include <stdint.h>

#define NMAX 100000
#define KK   27

__device__ float g_h0[NMAX * 32];
__device__ float g_h1[NMAX * 128];
__device__ float g_W1t[KK * 128 * 32];   // [k][n=128][c=32]  (col-major B)
__device__ float g_W2t[KK * 32 * 128];   // [k][n=32][c=128]
__device__ int   g_mask_w4;

// ---------------- helpers ----------------
__device__ __forceinline__ uint32_t smem_u32(const void* p) {
    uint32_t a;
    asm("{ .reg .u64 t; cvta.to.shared.u64 t, %1; cvt.u32.u64 %0, t; }" : "=r"(a) : "l"(p));
    return a;
}
__device__ __forceinline__ float gelu_f(float v) {
    return 0.5f * v * (1.0f + erff(v * 0.70710678118654752f));
}
__device__ __forceinline__ float to_tf32(float v) {
    uint32_t r; asm("cvt.rna.tf32.f32 %0, %1;" : "=r"(r) : "f"(v));
    return __uint_as_float(r);
}
__device__ __forceinline__ int mask_at(const void* m, int off, int w4) {
    if (w4) return ((const int*)m)[off];
    return (int)((const unsigned char*)m)[off];
}
__device__ __forceinline__ void cp16(uint32_t dst, const void* src, unsigned srcsz) {
    asm volatile("cp.async.cg.shared.global [%0], [%1], 16, %2;"
                 :: "r"(dst), "l"(src), "r"(srcsz) : "memory");
}
#define CP_COMMIT() asm volatile("cp.async.commit_group;" ::: "memory")
#define CP_WAIT1()  asm volatile("cp.async.wait_group 1;" ::: "memory")
#define CP_WAIT0()  asm volatile("cp.async.wait_group 0;" ::: "memory")

// m16n8k8 tf32 mma: A row-major (4 regs), B col-major (2 regs), C fp32 (4 regs)
__device__ __forceinline__ void mma8(float* c, const uint32_t* a, uint32_t b0, uint32_t b1) {
    asm volatile(
        "mma.sync.aligned.m16n8k8.row.col.f32.tf32.tf32.f32 "
        "{%0,%1,%2,%3}, {%4,%5,%6,%7}, {%8,%9}, {%0,%1,%2,%3};"
        : "+f"(c[0]), "+f"(c[1]), "+f"(c[2]), "+f"(c[3])
        : "r"(a[0]), "r"(a[1]), "r"(a[2]), "r"(a[3]), "r"(b0), "r"(b1));
}

// ---------------- prep: weight transpose + tf32 rounding ----------------
__global__ void k_prep(const float* __restrict__ W1, const float* __restrict__ W2) {
    int t = blockIdx.x * 256 + threadIdx.x;
    if (t < KK * 4096) {
        int k = t >> 12, r = t & 4095;
        // W1[k][c=r>>7][d=r&127] -> g_W1t[k][d][c]
        g_W1t[k * 4096 + (r & 127) * 32 + (r >> 7)] = to_tf32(W1[t]);
        // W2[k][c=r>>5][d=r&31]  -> g_W2t[k][d][c]
        g_W2t[k * 4096 + (r & 31) * 128 + (r >> 5)] = to_tf32(W2[t]);
    }
}

// ---------------- conv0 (SIMT fp32) ----------------
__global__ void k_conv0(const float* __restrict__ x, const float* __restrict__ Wc,
                        const float* __restrict__ g0, const float* __restrict__ b0,
                        const unsigned char* __restrict__ maskraw, int n) {
    __shared__ float sW[1024];
    int tid = threadIdx.x;
    if (blockIdx.x == 0 && tid == 0) {
        int w4 = 1;
        for (int t = 1; t < 400; ++t)
            if ((t & 3) != 0 && maskraw[t] != 0) { w4 = 0; break; }
        g_mask_w4 = w4;
    }
    for (int i = tid; i < 1024; i += 256) sW[i] = Wc[i];
    __syncthreads();

    int lane = tid & 31, w = tid >> 5;
    int row = blockIdx.x * 8 + w;
    if (row >= n) return;
    float xv = x[row * 32 + lane];
    float acc = 0.0f;
#pragma unroll
    for (int c = 0; c < 32; ++c) {
        float xs = __shfl_sync(0xffffffffu, xv, c);
        acc = fmaf(xs, sW[c * 32 + lane], acc);
    }
    float s = acc;
#pragma unroll
    for (int o = 16; o > 0; o >>= 1) s += __shfl_xor_sync(0xffffffffu, s, o);
    float mu = s * (1.0f / 32.0f);
    float d = acc - mu;
    float q = d * d;
#pragma unroll
    for (int o = 16; o > 0; o >>= 1) q += __shfl_xor_sync(0xffffffffu, q, o);
    float y = d * rsqrtf(q * (1.0f / 32.0f) + 1e-6f) * g0[lane] + b0[lane];
    g_h0[row * 32 + lane] = to_tf32(gelu_f(y));   // tf32-rounded for exact mma
}

// ---------------- conv1: 128x128 x (K32 x 27), mma.sync tf32 ----------------
// smem (bytes): A[s][128][36]f, B[s][128][36]f, sidx, gamma/beta, LN scratch
#define S1_STAGE 36864
#define S1_A(s)  ((s) * S1_STAGE)
#define S1_B(s)  ((s) * S1_STAGE + 18432)
#define S1_SIDX  73728
#define S1_G     87552
#define S1_BETA  88064
#define S1_RS    88576
#define S1_RQ    89600
#define S1_MU    90624
#define S1_SIG   91136
#define S1_SMEM  91648

__device__ __forceinline__ void fill1(uint32_t sb, const int* sidx, int k, int st, int tid) {
    int m = tid >> 1, half = tid & 1;
    int id = sidx[k * 128 + m];
    const char* src = (const char*)g_h0 + (size_t)(id < 0 ? 0 : id) * 128;
    unsigned sz = (id < 0) ? 0u : 16u;
    uint32_t ab = sb + S1_A(st) + m * 144;
#pragma unroll
    for (int i = 0; i < 4; i++) {
        int j = half * 4 + i;
        cp16(ab + j * 16, src + j * 16, sz);
    }
    const char* wsrc = (const char*)g_W1t + (size_t)k * 16384;
    uint32_t bb = sb + S1_B(st);
#pragma unroll
    for (int i = 0; i < 4; i++) {
        int c = tid + i * 256;
        int nr = c >> 3, j = c & 7;
        cp16(bb + nr * 144 + j * 16, wsrc + c * 16, 16);
    }
}

__global__ void __launch_bounds__(256, 2)
k_conv1(const int* __restrict__ nidx, const void* __restrict__ nmask,
        const float* __restrict__ g1v, const float* __restrict__ b1v, int n) {
    extern __shared__ char dyn[];
    uint32_t sb = smem_u32(dyn);
    int tid = threadIdx.x, wid = tid >> 5, lane = tid & 31;
    int g = lane >> 2, t4 = lane & 3;
    int row0 = blockIdx.x * 128;
    int* sidx = (int*)(dyn + S1_SIDX);
    float* sg  = (float*)(dyn + S1_G);
    float* sbe = (float*)(dyn + S1_BETA);

    if (tid < 128) { sg[tid] = g1v[tid]; sbe[tid] = b1v[tid]; }
    int w4 = g_mask_w4;
    for (int t = tid; t < KK * 128; t += 256) {
        int m = t / KK, k = t % KK;
        int nr = row0 + m; int id = -1;
        if (nr < n) {
            int off = nr * KK + k;
            if (mask_at(nmask, off, w4)) id = nidx[off];
        }
        sidx[k * 128 + m] = id;
    }
    __syncthreads();

    fill1(sb, sidx, 0, 0, tid); CP_COMMIT();
    fill1(sb, sidx, 1, 1, tid); CP_COMMIT();

    int mw = wid & 3, nw = wid >> 2;
    int mbase = mw * 32, nbase = nw * 64;
    float acc[2][8][4];
#pragma unroll
    for (int mt = 0; mt < 2; mt++)
#pragma unroll
        for (int nt = 0; nt < 8; nt++)
#pragma unroll
            for (int j = 0; j < 4; j++) acc[mt][nt][j] = 0.f;

    for (int k = 0; k < KK; k++) {
        int b = k & 1;
        if (k == KK - 1) CP_WAIT0(); else CP_WAIT1();
        __syncthreads();
        const uint32_t* A = (const uint32_t*)(dyn + S1_A(b));
        const uint32_t* B = (const uint32_t*)(dyn + S1_B(b));
#pragma unroll
        for (int kt = 0; kt < 4; kt++) {
            int kb = kt * 8;
            uint32_t a[2][4];
#pragma unroll
            for (int mt = 0; mt < 2; mt++) {
                int r = mbase + mt * 16 + g;
                a[mt][0] = A[r * 36 + kb + t4];
                a[mt][1] = A[(r + 8) * 36 + kb + t4];
                a[mt][2] = A[r * 36 + kb + t4 + 4];
                a[mt][3] = A[(r + 8) * 36 + kb + t4 + 4];
            }
#pragma unroll
            for (int nt = 0; nt < 8; nt++) {
                int cn = (nbase + nt * 8 + g) * 36 + kb + t4;
                uint32_t b0 = B[cn], b1 = B[cn + 4];
                mma8(acc[0][nt], a[0], b0, b1);
                mma8(acc[1][nt], a[1], b0, b1);
            }
        }
        __syncthreads();
        if (k + 2 < KK) { fill1(sb, sidx, k + 2, b, tid); CP_COMMIT(); }
    }

    // ---- fused LN(128) + GELU epilogue ----
    float* rs_ = (float*)(dyn + S1_RS);
    float* rq_ = (float*)(dyn + S1_RQ);
#pragma unroll
    for (int mt = 0; mt < 2; mt++)
#pragma unroll
        for (int rr = 0; rr < 2; rr++) {
            float s = 0.f, q = 0.f;
#pragma unroll
            for (int nt = 0; nt < 8; nt++) {
                float v0 = acc[mt][nt][rr * 2], v1 = acc[mt][nt][rr * 2 + 1];
                s += v0 + v1; q += v0 * v0 + v1 * v1;
            }
            s += __shfl_xor_sync(0xffffffffu, s, 1);
            s += __shfl_xor_sync(0xffffffffu, s, 2);
            q += __shfl_xor_sync(0xffffffffu, q, 1);
            q += __shfl_xor_sync(0xffffffffu, q, 2);
            if (t4 == 0) {
                int r = mbase + mt * 16 + rr * 8 + g;
                rs_[r * 2 + nw] = s; rq_[r * 2 + nw] = q;
            }
        }
    __syncthreads();
    float* smu = (float*)(dyn + S1_MU);
    float* ssg = (float*)(dyn + S1_SIG);
    if (tid < 128) {
        float s = rs_[tid * 2] + rs_[tid * 2 + 1];
        float q = rq_[tid * 2] + rq_[tid * 2 + 1];
        float mu = s * (1.0f / 128.0f);
        smu[tid] = mu;
        ssg[tid] = rsqrtf(q * (1.0f / 128.0f) - mu * mu + 1e-6f);
    }
    __syncthreads();
#pragma unroll
    for (int mt = 0; mt < 2; mt++)
#pragma unroll
        for (int rr = 0; rr < 2; rr++) {
            int r = mbase + mt * 16 + rr * 8 + g;
            int nr = row0 + r;
            if (nr >= n) continue;
            float mu = smu[r], rs = ssg[r];
            float* dst = g_h1 + (size_t)nr * 128;
#pragma unroll
            for (int nt = 0; nt < 8; nt++) {
                int c = nbase + nt * 8 + t4 * 2;
                float y0 = to_tf32(gelu_f((acc[mt][nt][rr * 2]     - mu) * rs * sg[c]     + sbe[c]));
                float y1 = to_tf32(gelu_f((acc[mt][nt][rr * 2 + 1] - mu) * rs * sg[c + 1] + sbe[c + 1]));
                *(float2*)(dst + c) = make_float2(y0, y1);
            }
        }
}

// ---------------- conv2: 128x32 x (K128 x 27), mma.sync tf32, k-split ----------------
// smem: A[s][128][132]f (67584), B[s][32][132]f (16896), sidx, gamma/beta
#define S2_STAGE 84480
#define S2_A(s)  ((s) * S2_STAGE)
#define S2_B(s)  ((s) * S2_STAGE + 67584)
#define S2_SIDX  168960
#define S2_G     182784
#define S2_BETA  182912
#define S2_SMEM  183040

__device__ __forceinline__ void fill2(uint32_t sb, const int* sidx, int k, int st, int tid) {
    int m = tid >> 1, half = tid & 1;
    int id = sidx[k * 128 + m];
    const char* src = (const char*)g_h1 + (size_t)(id < 0 ? 0 : id) * 512;
    unsigned sz = (id < 0) ? 0u : 16u;
    uint32_t ab = sb + S2_A(st) + m * 528;
#pragma unroll
    for (int i = 0; i < 16; i++) {
        int j = half * 16 + i;
        cp16(ab + j * 16, src + j * 16, sz);
    }
    const char* wsrc = (const char*)g_W2t + (size_t)k * 16384;
    uint32_t bb = sb + S2_B(st);
#pragma unroll
    for (int i = 0; i < 4; i++) {
        int c = tid + i * 256;
        int nr = c >> 5, j = c & 31;
        cp16(bb + nr * 528 + j * 16, wsrc + c * 16, 16);
    }
}

__global__ void __launch_bounds__(256, 1)
k_conv2(const float* __restrict__ x, const int* __restrict__ nidx,
        const void* __restrict__ nmask, const float* __restrict__ g2v,
        const float* __restrict__ b2v, float* __restrict__ out, int n) {
    extern __shared__ char dyn[];
    uint32_t sb = smem_u32(dyn);
    int tid = threadIdx.x, wid = tid >> 5, lane = tid & 31;
    int g = lane >> 2, t4 = lane & 3;
    int row0 = blockIdx.x * 128;
    int* sidx = (int*)(dyn + S2_SIDX);
    float* sg  = (float*)(dyn + S2_G);
    float* sbe = (float*)(dyn + S2_BETA);

    if (tid < 32) { sg[tid] = g2v[tid]; sbe[tid] = b2v[tid]; }
    int w4 = g_mask_w4;
    for (int t = tid; t < KK * 128; t += 256) {
        int m = t / KK, k = t % KK;
        int nr = row0 + m; int id = -1;
        if (nr < n) {
            int off = nr * KK + k;
            if (mask_at(nmask, off, w4)) id = nidx[off];
        }
        sidx[k * 128 + m] = id;
    }
    __syncthreads();

    fill2(sb, sidx, 0, 0, tid); CP_COMMIT();
    fill2(sb, sidx, 1, 1, tid); CP_COMMIT();

    int mw = wid & 3, kh = wid >> 2;          // k-half split across warp pairs
    int mbase = mw * 32, khbase = kh * 64;
    float acc[2][4][4];
#pragma unroll
    for (int mt = 0; mt < 2; mt++)
#pragma unroll
        for (int nt = 0; nt < 4; nt++)
#pragma unroll
            for (int j = 0; j < 4; j++) acc[mt][nt][j] = 0.f;

    for (int k = 0; k < KK; k++) {
        int b = k & 1;
        if (k == KK - 1) CP_WAIT0(); else CP_WAIT1();
        __syncthreads();
        const uint32_t* A = (const uint32_t*)(dyn + S2_A(b));
        const uint32_t* B = (const uint32_t*)(dyn + S2_B(b));
#pragma unroll
        for (int kt = 0; kt < 8; kt++) {
            int kb = khbase + kt * 8;
            uint32_t a[2][4];
#pragma unroll
            for (int mt = 0; mt < 2; mt++) {
                int r = mbase + mt * 16 + g;
                a[mt][0] = A[r * 132 + kb + t4];
                a[mt][1] = A[(r + 8) * 132 + kb + t4];
                a[mt][2] = A[r * 132 + kb + t4 + 4];
                a[mt][3] = A[(r + 8) * 132 + kb + t4 + 4];
            }
#pragma unroll
            for (int nt = 0; nt < 4; nt++) {
                int cn = (nt * 8 + g) * 132 + kb + t4;
                uint32_t b0 = B[cn], b1 = B[cn + 4];
                mma8(acc[0][nt], a[0], b0, b1);
                mma8(acc[1][nt], a[1], b0, b1);
            }
        }
        __syncthreads();
        if (k + 2 < KK) { fill2(sb, sidx, k + 2, b, tid); CP_COMMIT(); }
    }

    // ---- k-half reduction via smem (reuse stage0 A region), P[128][34] ----
    float* P = (float*)dyn;
    if (kh == 1) {
#pragma unroll
        for (int mt = 0; mt < 2; mt++)
#pragma unroll
            for (int nt = 0; nt < 4; nt++) {
                int r = mbase + mt * 16 + g, c = nt * 8 + t4 * 2;
                *(float2*)&P[r * 34 + c]       = make_float2(acc[mt][nt][0], acc[mt][nt][1]);
                *(float2*)&P[(r + 8) * 34 + c] = make_float2(acc[mt][nt][2], acc[mt][nt][3]);
            }
    }
    __syncthreads();
    if (kh == 0) {
#pragma unroll
        for (int mt = 0; mt < 2; mt++)
#pragma unroll
            for (int nt = 0; nt < 4; nt++) {
                int r = mbase + mt * 16 + g, c = nt * 8 + t4 * 2;
                float2 p0 = *(float2*)&P[r * 34 + c];
                float2 p1 = *(float2*)&P[(r + 8) * 34 + c];
                acc[mt][nt][0] += p0.x; acc[mt][nt][1] += p0.y;
                acc[mt][nt][2] += p1.x; acc[mt][nt][3] += p1.y;
            }
        // ---- fused LN(32) + residual + GELU ----
#pragma unroll
        for (int mt = 0; mt < 2; mt++)
#pragma unroll
            for (int rr = 0; rr < 2; rr++) {
                float s = 0.f, q = 0.f;
#pragma unroll
                for (int nt = 0; nt < 4; nt++) {
                    float v0 = acc[mt][nt][rr * 2], v1 = acc[mt][nt][rr * 2 + 1];
                    s += v0 + v1; q += v0 * v0 + v1 * v1;
                }
                s += __shfl_xor_sync(0xffffffffu, s, 1);
                s += __shfl_xor_sync(0xffffffffu, s, 2);
                q += __shfl_xor_sync(0xffffffffu, q, 1);
                q += __shfl_xor_sync(0xffffffffu, q, 2);
                float mu = s * (1.0f / 32.0f);
                float rs = rsqrtf(q * (1.0f / 32.0f) - mu * mu + 1e-6f);
                int r = mbase + mt * 16 + rr * 8 + g;
                int nr = row0 + r;
                if (nr >= n) continue;
#pragma unroll
                for (int nt = 0; nt < 4; nt++) {
                    int c = nt * 8 + t4 * 2;
                    float2 xv = *(const float2*)(x + (size_t)nr * 32 + c);
                    float y0 = gelu_f((acc[mt][nt][rr * 2]     - mu) * rs * sg[c]     + sbe[c]     + xv.x);
                    float y1 = gelu_f((acc[mt][nt][rr * 2 + 1] - mu) * rs * sg[c + 1] + sbe[c + 1] + xv.y);
                    *(float2*)(out + (size_t)nr * 32 + c) = make_float2(y0, y1);
                }
            }
    }
}

// ---------------------------------------------------------------------------
extern "C" void kernel_launch(void* const* d_in, const int* in_sizes, int n_in,
                              void* d_out, int out_size) {
    const float* x   = (const float*)d_in[0];
    const int*   nid = (const int*)d_in[1];
    const void*  msk = (const void*)d_in[2];
    const float* Wc  = (const float*)d_in[3];
    const float* g0  = (const float*)d_in[4];
    const float* b0  = (const float*)d_in[5];
    const float* W1  = (const float*)d_in[6];
    const float* g1  = (const float*)d_in[7];
    const float* b1  = (const float*)d_in[8];
    const float* W2  = (const float*)d_in[9];
    const float* g2  = (const float*)d_in[10];
    const float* b2  = (const float*)d_in[11];
    float* out = (float*)d_out;
    int n = in_sizes[0] / 32;

    cudaFuncSetAttribute(k_conv1, cudaFuncAttributeMaxDynamicSharedMemorySize, S1_SMEM);
    cudaFuncSetAttribute(k_conv2, cudaFuncAttributeMaxDynamicSharedMemorySize, S2_SMEM);

    k_prep<<<(KK * 4096 + 255) / 256, 256>>>(W1, W2);
    k_conv0<<<(n + 7) / 8, 256>>>(x, Wc, g0, b0, (const unsigned char*)msk, n);
    int nb = (n + 127) / 128;
    k_conv1<<<nb, 256, S1_SMEM>>>(nid, msk, g1, b1, n);
    k_conv2<<<nb, 256, S2_SMEM>>>(x, nid, msk, g2, b2, out, n);
}

// round 10
// speedup vs baseline: 2.2548x; 1.0685x over previous
#include <cuda_runtime.h>
#include <math.h>
#include <stdint.h>

#define NMAX 100000
#define KK   27

__device__ float g_h0[NMAX * 32];
__device__ float g_h1[NMAX * 128];
__device__ float g_W1t[KK * 128 * 32];   // [k][n=128][c=32]  (col-major B)
__device__ float g_W2t[KK * 32 * 128];   // [k][n=32][c=128]
__device__ int   g_mask_w4;

// ---------------- helpers ----------------
__device__ __forceinline__ uint32_t smem_u32(const void* p) {
    uint32_t a;
    asm("{ .reg .u64 t; cvta.to.shared.u64 t, %1; cvt.u32.u64 %0, t; }" : "=r"(a) : "l"(p));
    return a;
}
__device__ __forceinline__ float gelu_f(float v) {
    return 0.5f * v * (1.0f + erff(v * 0.70710678118654752f));
}
__device__ __forceinline__ float to_tf32(float v) {
    uint32_t r; asm("cvt.rna.tf32.f32 %0, %1;" : "=r"(r) : "f"(v));
    return __uint_as_float(r);
}
__device__ __forceinline__ int mask_at(const void* m, int off, int w4) {
    if (w4) return ((const int*)m)[off];
    return (int)((const unsigned char*)m)[off];
}
__device__ __forceinline__ void cp16(uint32_t dst, const void* src, unsigned srcsz) {
    asm volatile("cp.async.cg.shared.global [%0], [%1], 16, %2;"
                 :: "r"(dst), "l"(src), "r"(srcsz) : "memory");
}
#define CP_COMMIT() asm volatile("cp.async.commit_group;" ::: "memory")
#define CP_WAIT1()  asm volatile("cp.async.wait_group 1;" ::: "memory")
#define CP_WAIT0()  asm volatile("cp.async.wait_group 0;" ::: "memory")

// m16n8k8 tf32 mma: A row-major (4 regs), B col-major (2 regs), C fp32 (4 regs)
__device__ __forceinline__ void mma8(float* c, const uint32_t* a, uint32_t b0, uint32_t b1) {
    asm volatile(
        "mma.sync.aligned.m16n8k8.row.col.f32.tf32.tf32.f32 "
        "{%0,%1,%2,%3}, {%4,%5,%6,%7}, {%8,%9}, {%0,%1,%2,%3};"
        : "+f"(c[0]), "+f"(c[1]), "+f"(c[2]), "+f"(c[3])
        : "r"(a[0]), "r"(a[1]), "r"(a[2]), "r"(a[3]), "r"(b0), "r"(b1));
}

// ---------------- prep: weight transpose + tf32 rounding ----------------
__global__ void k_prep(const float* __restrict__ W1, const float* __restrict__ W2) {
    int t = blockIdx.x * 256 + threadIdx.x;
    if (t < KK * 4096) {
        int k = t >> 12, r = t & 4095;
        g_W1t[k * 4096 + (r & 127) * 32 + (r >> 7)] = to_tf32(W1[t]);
        g_W2t[k * 4096 + (r & 31) * 128 + (r >> 5)] = to_tf32(W2[t]);
    }
}

// ---------------- conv0 (SIMT fp32) ----------------
__global__ void k_conv0(const float* __restrict__ x, const float* __restrict__ Wc,
                        const float* __restrict__ g0, const float* __restrict__ b0,
                        const unsigned char* __restrict__ maskraw, int n) {
    __shared__ float sW[1024];
    int tid = threadIdx.x;
    if (blockIdx.x == 0 && tid == 0) {
        int w4 = 1;
        for (int t = 1; t < 400; ++t)
            if ((t & 3) != 0 && maskraw[t] != 0) { w4 = 0; break; }
        g_mask_w4 = w4;
    }
    for (int i = tid; i < 1024; i += 256) sW[i] = Wc[i];
    __syncthreads();

    int lane = tid & 31, w = tid >> 5;
    int row = blockIdx.x * 8 + w;
    if (row >= n) return;
    float xv = x[row * 32 + lane];
    float acc = 0.0f;
#pragma unroll
    for (int c = 0; c < 32; ++c) {
        float xs = __shfl_sync(0xffffffffu, xv, c);
        acc = fmaf(xs, sW[c * 32 + lane], acc);
    }
    float s = acc;
#pragma unroll
    for (int o = 16; o > 0; o >>= 1) s += __shfl_xor_sync(0xffffffffu, s, o);
    float mu = s * (1.0f / 32.0f);
    float d = acc - mu;
    float q = d * d;
#pragma unroll
    for (int o = 16; o > 0; o >>= 1) q += __shfl_xor_sync(0xffffffffu, q, o);
    float y = d * rsqrtf(q * (1.0f / 32.0f) + 1e-6f) * g0[lane] + b0[lane];
    g_h0[row * 32 + lane] = to_tf32(gelu_f(y));
}

// ---------------- conv1: 128x128 x (K32 x 27), mma.sync tf32 ----------------
#define S1_STAGE 36864
#define S1_A(s)  ((s) * S1_STAGE)
#define S1_B(s)  ((s) * S1_STAGE + 18432)
#define S1_SIDX  73728
#define S1_G     87552
#define S1_BETA  88064
#define S1_RS    88576
#define S1_RQ    89600
#define S1_MU    90624
#define S1_SIG   91136
#define S1_SMEM  91648

__device__ __forceinline__ void fill1(uint32_t sb, const int* sidx, int k, int st, int tid) {
    int m = tid >> 1, half = tid & 1;
    int id = sidx[k * 128 + m];
    const char* src = (const char*)g_h0 + (size_t)(id < 0 ? 0 : id) * 128;
    unsigned sz = (id < 0) ? 0u : 16u;
    uint32_t ab = sb + S1_A(st) + m * 144;
#pragma unroll
    for (int i = 0; i < 4; i++) {
        int j = half * 4 + i;
        cp16(ab + j * 16, src + j * 16, sz);
    }
    const char* wsrc = (const char*)g_W1t + (size_t)k * 16384;
    uint32_t bb = sb + S1_B(st);
#pragma unroll
    for (int i = 0; i < 4; i++) {
        int c = tid + i * 256;
        int nr = c >> 3, j = c & 7;
        cp16(bb + nr * 144 + j * 16, wsrc + c * 16, 16);
    }
}

__global__ void __launch_bounds__(256, 2)
k_conv1(const int* __restrict__ nidx, const void* __restrict__ nmask,
        const float* __restrict__ g1v, const float* __restrict__ b1v, int n) {
    extern __shared__ char dyn[];
    uint32_t sb = smem_u32(dyn);
    int tid = threadIdx.x, wid = tid >> 5, lane = tid & 31;
    int g = lane >> 2, t4 = lane & 3;
    int row0 = blockIdx.x * 128;
    int* sidx = (int*)(dyn + S1_SIDX);
    float* sg  = (float*)(dyn + S1_G);
    float* sbe = (float*)(dyn + S1_BETA);

    if (tid < 128) { sg[tid] = g1v[tid]; sbe[tid] = b1v[tid]; }
    int w4 = g_mask_w4;
    for (int t = tid; t < KK * 128; t += 256) {
        int m = t / KK, k = t % KK;
        int nr = row0 + m; int id = -1;
        if (nr < n) {
            int off = nr * KK + k;
            if (mask_at(nmask, off, w4)) id = nidx[off];
        }
        sidx[k * 128 + m] = id;
    }
    __syncthreads();

    fill1(sb, sidx, 0, 0, tid); CP_COMMIT();
    fill1(sb, sidx, 1, 1, tid); CP_COMMIT();

    int mw = wid & 3, nw = wid >> 2;
    int mbase = mw * 32, nbase = nw * 64;
    float acc[2][8][4];
#pragma unroll
    for (int mt = 0; mt < 2; mt++)
#pragma unroll
        for (int nt = 0; nt < 8; nt++)
#pragma unroll
            for (int j = 0; j < 4; j++) acc[mt][nt][j] = 0.f;

    for (int k = 0; k < KK; k++) {
        int b = k & 1;
        if (k == KK - 1) CP_WAIT0(); else CP_WAIT1();
        __syncthreads();
        const uint32_t* A = (const uint32_t*)(dyn + S1_A(b));
        const uint32_t* B = (const uint32_t*)(dyn + S1_B(b));
#pragma unroll
        for (int kt = 0; kt < 4; kt++) {
            int kb = kt * 8;
            uint32_t a[2][4];
#pragma unroll
            for (int mt = 0; mt < 2; mt++) {
                int r = mbase + mt * 16 + g;
                a[mt][0] = A[r * 36 + kb + t4];
                a[mt][1] = A[(r + 8) * 36 + kb + t4];
                a[mt][2] = A[r * 36 + kb + t4 + 4];
                a[mt][3] = A[(r + 8) * 36 + kb + t4 + 4];
            }
#pragma unroll
            for (int nt = 0; nt < 8; nt++) {
                int cn = (nbase + nt * 8 + g) * 36 + kb + t4;
                uint32_t b0 = B[cn], b1 = B[cn + 4];
                mma8(acc[0][nt], a[0], b0, b1);
                mma8(acc[1][nt], a[1], b0, b1);
            }
        }
        __syncthreads();
        if (k + 2 < KK) { fill1(sb, sidx, k + 2, b, tid); CP_COMMIT(); }
    }

    float* rs_ = (float*)(dyn + S1_RS);
    float* rq_ = (float*)(dyn + S1_RQ);
#pragma unroll
    for (int mt = 0; mt < 2; mt++)
#pragma unroll
        for (int rr = 0; rr < 2; rr++) {
            float s = 0.f, q = 0.f;
#pragma unroll
            for (int nt = 0; nt < 8; nt++) {
                float v0 = acc[mt][nt][rr * 2], v1 = acc[mt][nt][rr * 2 + 1];
                s += v0 + v1; q += v0 * v0 + v1 * v1;
            }
            s += __shfl_xor_sync(0xffffffffu, s, 1);
            s += __shfl_xor_sync(0xffffffffu, s, 2);
            q += __shfl_xor_sync(0xffffffffu, q, 1);
            q += __shfl_xor_sync(0xffffffffu, q, 2);
            if (t4 == 0) {
                int r = mbase + mt * 16 + rr * 8 + g;
                rs_[r * 2 + nw] = s; rq_[r * 2 + nw] = q;
            }
        }
    __syncthreads();
    float* smu = (float*)(dyn + S1_MU);
    float* ssg = (float*)(dyn + S1_SIG);
    if (tid < 128) {
        float s = rs_[tid * 2] + rs_[tid * 2 + 1];
        float q = rq_[tid * 2] + rq_[tid * 2 + 1];
        float mu = s * (1.0f / 128.0f);
        smu[tid] = mu;
        ssg[tid] = rsqrtf(q * (1.0f / 128.0f) - mu * mu + 1e-6f);
    }
    __syncthreads();
#pragma unroll
    for (int mt = 0; mt < 2; mt++)
#pragma unroll
        for (int rr = 0; rr < 2; rr++) {
            int r = mbase + mt * 16 + rr * 8 + g;
            int nr = row0 + r;
            if (nr >= n) continue;
            float mu = smu[r], rs = ssg[r];
            float* dst = g_h1 + (size_t)nr * 128;
#pragma unroll
            for (int nt = 0; nt < 8; nt++) {
                int c = nbase + nt * 8 + t4 * 2;
                float y0 = to_tf32(gelu_f((acc[mt][nt][rr * 2]     - mu) * rs * sg[c]     + sbe[c]));
                float y1 = to_tf32(gelu_f((acc[mt][nt][rr * 2 + 1] - mu) * rs * sg[c + 1] + sbe[c + 1]));
                *(float2*)(dst + c) = make_float2(y0, y1);
            }
        }
}

// ---------------- conv2: 256x32 x (K64 x 54), mma.sync tf32 ----------------
// 512 threads = 8 m-warps x 2 k-half warps. A[s][256][68]f, B[s][32][68]f.
#define S2_ASTG  69632               /* 256 * 272 bytes */
#define S2_A(s)  ((s) * S2_ASTG)
#define S2_B(s)  (139264 + (s) * 8704)
#define S2_SIDX  156672
#define S2_G     184320
#define S2_BETA  184448
#define S2_SMEM  184576

__device__ __forceinline__ void fill2(uint32_t sb, const int* sidx, int k, int h,
                                      int st, int tid) {
    int m = tid >> 1, half = tid & 1;
    int id = sidx[k * 256 + m];
    const char* src = (const char*)g_h1 + (size_t)(id < 0 ? 0 : id) * 512 + h * 256;
    unsigned sz = (id < 0) ? 0u : 16u;
    uint32_t ab = sb + S2_A(st) + m * 272;
#pragma unroll
    for (int i = 0; i < 8; i++) {
        int j = half * 8 + i;
        cp16(ab + j * 16, src + j * 16, sz);
    }
    const char* wsrc = (const char*)g_W2t + (size_t)k * 16384 + h * 256;
    int nr = tid >> 4, j = tid & 15;
    cp16(sb + S2_B(st) + nr * 272 + j * 16, wsrc + nr * 512 + j * 16, 16);
}

__global__ void __launch_bounds__(512, 1)
k_conv2(const float* __restrict__ x, const int* __restrict__ nidx,
        const void* __restrict__ nmask, const float* __restrict__ g2v,
        const float* __restrict__ b2v, float* __restrict__ out, int n) {
    extern __shared__ char dyn[];
    uint32_t sb = smem_u32(dyn);
    int tid = threadIdx.x, wid = tid >> 5, lane = tid & 31;
    int g = lane >> 2, t4 = lane & 3;
    int row0 = blockIdx.x * 256;
    int* sidx = (int*)(dyn + S2_SIDX);
    float* sg  = (float*)(dyn + S2_G);
    float* sbe = (float*)(dyn + S2_BETA);

    if (tid < 32) { sg[tid] = g2v[tid]; sbe[tid] = b2v[tid]; }
    int w4 = g_mask_w4;
    for (int t = tid; t < KK * 256; t += 512) {
        int m = t / KK, k = t % KK;
        int nr = row0 + m; int id = -1;
        if (nr < n) {
            int off = nr * KK + k;
            if (mask_at(nmask, off, w4)) id = nidx[off];
        }
        sidx[k * 256 + m] = id;
    }
    __syncthreads();

    fill2(sb, sidx, 0, 0, 0, tid); CP_COMMIT();
    fill2(sb, sidx, 0, 1, 1, tid); CP_COMMIT();

    int mw = wid & 7, kh = wid >> 3;        // 8 m-warps x 2 k-halves
    int mbase = mw * 32, kqb = kh * 32;
    float acc[2][4][4];
#pragma unroll
    for (int mt = 0; mt < 2; mt++)
#pragma unroll
        for (int nt = 0; nt < 4; nt++)
#pragma unroll
            for (int j = 0; j < 4; j++) acc[mt][nt][j] = 0.f;

    const int NIT = KK * 2;                 // 54 iterations of K=64
    for (int kk = 0; kk < NIT; kk++) {
        int b = kk & 1;
        if (kk == NIT - 1) CP_WAIT0(); else CP_WAIT1();
        __syncthreads();
        const uint32_t* A = (const uint32_t*)(dyn + S2_A(b));
        const uint32_t* B = (const uint32_t*)(dyn + S2_B(b));
#pragma unroll
        for (int kt = 0; kt < 4; kt++) {
            int kb = kqb + kt * 8;
            uint32_t a[2][4];
#pragma unroll
            for (int mt = 0; mt < 2; mt++) {
                int r = mbase + mt * 16 + g;
                a[mt][0] = A[r * 68 + kb + t4];
                a[mt][1] = A[(r + 8) * 68 + kb + t4];
                a[mt][2] = A[r * 68 + kb + t4 + 4];
                a[mt][3] = A[(r + 8) * 68 + kb + t4 + 4];
            }
#pragma unroll
            for (int nt = 0; nt < 4; nt++) {
                int cn = (nt * 8 + g) * 68 + kb + t4;
                uint32_t b0 = B[cn], b1 = B[cn + 4];
                mma8(acc[0][nt], a[0], b0, b1);
                mma8(acc[1][nt], a[1], b0, b1);
            }
        }
        __syncthreads();
        if (kk + 2 < NIT) {
            int nk = kk + 2;
            fill2(sb, sidx, nk >> 1, nk & 1, b, tid); CP_COMMIT();
        }
    }

    // ---- k-half reduction via smem (reuse stage0 A region), P[256][34] ----
    float* P = (float*)dyn;
    if (kh == 1) {
#pragma unroll
        for (int mt = 0; mt < 2; mt++)
#pragma unroll
            for (int nt = 0; nt < 4; nt++) {
                int r = mbase + mt * 16 + g, c = nt * 8 + t4 * 2;
                *(float2*)&P[r * 34 + c]       = make_float2(acc[mt][nt][0], acc[mt][nt][1]);
                *(float2*)&P[(r + 8) * 34 + c] = make_float2(acc[mt][nt][2], acc[mt][nt][3]);
            }
    }
    __syncthreads();
    if (kh == 0) {
#pragma unroll
        for (int mt = 0; mt < 2; mt++)
#pragma unroll
            for (int nt = 0; nt < 4; nt++) {
                int r = mbase + mt * 16 + g, c = nt * 8 + t4 * 2;
                float2 p0 = *(float2*)&P[r * 34 + c];
                float2 p1 = *(float2*)&P[(r + 8) * 34 + c];
                acc[mt][nt][0] += p0.x; acc[mt][nt][1] += p0.y;
                acc[mt][nt][2] += p1.x; acc[mt][nt][3] += p1.y;
            }
        // ---- fused LN(32) + residual + GELU ----
#pragma unroll
        for (int mt = 0; mt < 2; mt++)
#pragma unroll
            for (int rr = 0; rr < 2; rr++) {
                float s = 0.f, q = 0.f;
#pragma unroll
                for (int nt = 0; nt < 4; nt++) {
                    float v0 = acc[mt][nt][rr * 2], v1 = acc[mt][nt][rr * 2 + 1];
                    s += v0 + v1; q += v0 * v0 + v1 * v1;
                }
                s += __shfl_xor_sync(0xffffffffu, s, 1);
                s += __shfl_xor_sync(0xffffffffu, s, 2);
                q += __shfl_xor_sync(0xffffffffu, q, 1);
                q += __shfl_xor_sync(0xffffffffu, q, 2);
                float mu = s * (1.0f / 32.0f);
                float rs = rsqrtf(q * (1.0f / 32.0f) - mu * mu + 1e-6f);
                int r = mbase + mt * 16 + rr * 8 + g;
                int nr = row0 + r;
                if (nr >= n) continue;
#pragma unroll
                for (int nt = 0; nt < 4; nt++) {
                    int c = nt * 8 + t4 * 2;
                    float2 xv = *(const float2*)(x + (size_t)nr * 32 + c);
                    float y0 = gelu_f((acc[mt][nt][rr * 2]     - mu) * rs * sg[c]     + sbe[c]     + xv.x);
                    float y1 = gelu_f((acc[mt][nt][rr * 2 + 1] - mu) * rs * sg[c + 1] + sbe[c + 1] + xv.y);
                    *(float2*)(out + (size_t)nr * 32 + c) = make_float2(y0, y1);
                }
            }
    }
}

// ---------------------------------------------------------------------------
extern "C" void kernel_launch(void* const* d_in, const int* in_sizes, int n_in,
                              void* d_out, int out_size) {
    const float* x   = (const float*)d_in[0];
    const int*   nid = (const int*)d_in[1];
    const void*  msk = (const void*)d_in[2];
    const float* Wc  = (const float*)d_in[3];
    const float* g0  = (const float*)d_in[4];
    const float* b0  = (const float*)d_in[5];
    const float* W1  = (const float*)d_in[6];
    const float* g1  = (const float*)d_in[7];
    const float* b1  = (const float*)d_in[8];
    const float* W2  = (const float*)d_in[9];
    const float* g2  = (const float*)d_in[10];
    const float* b2  = (const float*)d_in[11];
    float* out = (float*)d_out;
    int n = in_sizes[0] / 32;

    cudaFuncSetAttribute(k_conv1, cudaFuncAttributeMaxDynamicSharedMemorySize, S1_SMEM);
    cudaFuncSetAttribute(k_conv2, cudaFuncAttributeMaxDynamicSharedMemorySize, S2_SMEM);

    k_prep<<<(KK * 4096 + 255) / 256, 256>>>(W1, W2);
    k_conv0<<<(n + 7) / 8, 256>>>(x, Wc, g0, b0, (const unsigned char*)msk, n);
    int nb1 = (n + 127) / 128;
    k_conv1<<<nb1, 256, S1_SMEM>>>(nid, msk, g1, b1, n);
    int nb2 = (n + 255) / 256;
    k_conv2<<<nb2, 512, S2_SMEM>>>(x, nid, msk, g2, b2, out, n);
}

// round 11
// speedup vs baseline: 2.7724x; 1.2296x over previous
#include <cuda_runtime.h>
#include <math.h>
#include <stdint.h>

#define NMAX 100000
#define KK   27

__device__ float g_h0[NMAX * 32];
__device__ float g_h1[NMAX * 128];
__device__ float g_W1t[KK * 128 * 32];   // [k][n=128][c=32]  (col-major B)
__device__ float g_W2t[KK * 32 * 128];   // [k][n=32][c=128]
__device__ int   g_mask_w4;

// ---------------- helpers ----------------
__device__ __forceinline__ uint32_t smem_u32(const void* p) {
    uint32_t a;
    asm("{ .reg .u64 t; cvta.to.shared.u64 t, %1; cvt.u32.u64 %0, t; }" : "=r"(a) : "l"(p));
    return a;
}
__device__ __forceinline__ float gelu_f(float v) {
    return 0.5f * v * (1.0f + erff(v * 0.70710678118654752f));
}
__device__ __forceinline__ float to_tf32(float v) {
    uint32_t r; asm("cvt.rna.tf32.f32 %0, %1;" : "=r"(r) : "f"(v));
    return __uint_as_float(r);
}
__device__ __forceinline__ int mask_at(const void* m, int off, int w4) {
    if (w4) return ((const int*)m)[off];
    return (int)((const unsigned char*)m)[off];
}
__device__ __forceinline__ void cp16(uint32_t dst, const void* src, unsigned srcsz) {
    asm volatile("cp.async.cg.shared.global [%0], [%1], 16, %2;"
                 :: "r"(dst), "l"(src), "r"(srcsz) : "memory");
}
#define CP_COMMIT() asm volatile("cp.async.commit_group;" ::: "memory")
#define CP_WAIT0()  asm volatile("cp.async.wait_group 0;" ::: "memory")
#define CP_WAIT1()  asm volatile("cp.async.wait_group 1;" ::: "memory")
#define CP_WAIT2()  asm volatile("cp.async.wait_group 2;" ::: "memory")
#define CP_WAIT_FOR(kk, NIT) do { \
    if ((kk) + 2 < (NIT)) CP_WAIT2(); \
    else if ((kk) + 1 < (NIT)) CP_WAIT1(); \
    else CP_WAIT0(); } while (0)

// m16n8k8 tf32 mma
__device__ __forceinline__ void mma8(float* c, const uint32_t* a, uint32_t b0, uint32_t b1) {
    asm volatile(
        "mma.sync.aligned.m16n8k8.row.col.f32.tf32.tf32.f32 "
        "{%0,%1,%2,%3}, {%4,%5,%6,%7}, {%8,%9}, {%0,%1,%2,%3};"
        : "+f"(c[0]), "+f"(c[1]), "+f"(c[2]), "+f"(c[3])
        : "r"(a[0]), "r"(a[1]), "r"(a[2]), "r"(a[3]), "r"(b0), "r"(b1));
}

// ---------------- prep: weight transpose + tf32 rounding ----------------
__global__ void k_prep(const float* __restrict__ W1, const float* __restrict__ W2) {
    int t = blockIdx.x * 256 + threadIdx.x;
    if (t < KK * 4096) {
        int k = t >> 12, r = t & 4095;
        g_W1t[k * 4096 + (r & 127) * 32 + (r >> 7)] = to_tf32(W1[t]);
        g_W2t[k * 4096 + (r & 31) * 128 + (r >> 5)] = to_tf32(W2[t]);
    }
}

// ---------------- conv0 (SIMT fp32) ----------------
__global__ void k_conv0(const float* __restrict__ x, const float* __restrict__ Wc,
                        const float* __restrict__ g0, const float* __restrict__ b0,
                        const unsigned char* __restrict__ maskraw, int n) {
    __shared__ float sW[1024];
    int tid = threadIdx.x;
    if (blockIdx.x == 0 && tid == 0) {
        int w4 = 1;
        for (int t = 1; t < 400; ++t)
            if ((t & 3) != 0 && maskraw[t] != 0) { w4 = 0; break; }
        g_mask_w4 = w4;
    }
    for (int i = tid; i < 1024; i += 256) sW[i] = Wc[i];
    __syncthreads();

    int lane = tid & 31, w = tid >> 5;
    int row = blockIdx.x * 8 + w;
    if (row >= n) return;
    float xv = x[row * 32 + lane];
    float acc = 0.0f;
#pragma unroll
    for (int c = 0; c < 32; ++c) {
        float xs = __shfl_sync(0xffffffffu, xv, c);
        acc = fmaf(xs, sW[c * 32 + lane], acc);
    }
    float s = acc;
#pragma unroll
    for (int o = 16; o > 0; o >>= 1) s += __shfl_xor_sync(0xffffffffu, s, o);
    float mu = s * (1.0f / 32.0f);
    float d = acc - mu;
    float q = d * d;
#pragma unroll
    for (int o = 16; o > 0; o >>= 1) q += __shfl_xor_sync(0xffffffffu, q, o);
    float y = d * rsqrtf(q * (1.0f / 32.0f) + 1e-6f) * g0[lane] + b0[lane];
    g_h0[row * 32 + lane] = to_tf32(gelu_f(y));
}

// ---------------- conv1: 128x128, K=16 chunks x 54, depth-4 ----------------
// A[s][128][20]f, B[s][128][20]f (stride 20 floats = 80B, conflict-free)
#define T1_A(s)  ((s) * 10240)
#define T1_B(s)  (40960 + (s) * 10240)
#define T1_SIDX  81920
#define T1_G     95744
#define T1_BETA  96256
#define T1_RS    96768
#define T1_RQ    97792
#define T1_MU    98816
#define T1_SIG   99328
#define T1_SMEM  99840

__device__ __forceinline__ void fill1(uint32_t sb, const int* sidx, int kk, int st, int tid) {
    int k = kk >> 1, h = kk & 1;
#pragma unroll
    for (int i = 0; i < 2; i++) {           // A: 512 chunks
        int c = tid + i * 256;
        int row = c >> 2, j = c & 3;
        int id = sidx[k * 128 + row];
        const char* src = (const char*)g_h0 + (size_t)(id < 0 ? 0 : id) * 128 + h * 64 + j * 16;
        cp16(sb + T1_A(st) + row * 80 + j * 16, src, (id < 0) ? 0u : 16u);
    }
    const char* wsrc = (const char*)g_W1t + (size_t)k * 16384 + h * 64;
#pragma unroll
    for (int i = 0; i < 2; i++) {           // B: 512 chunks
        int c = tid + i * 256;
        int nr = c >> 2, j = c & 3;
        cp16(sb + T1_B(st) + nr * 80 + j * 16, wsrc + nr * 128 + j * 16, 16);
    }
}

__global__ void __launch_bounds__(256, 2)
k_conv1(const int* __restrict__ nidx, const void* __restrict__ nmask,
        const float* __restrict__ g1v, const float* __restrict__ b1v, int n) {
    extern __shared__ char dyn[];
    uint32_t sb = smem_u32(dyn);
    int tid = threadIdx.x, wid = tid >> 5, lane = tid & 31;
    int g = lane >> 2, t4 = lane & 3;
    int row0 = blockIdx.x * 128;
    int* sidx = (int*)(dyn + T1_SIDX);
    float* sg  = (float*)(dyn + T1_G);
    float* sbe = (float*)(dyn + T1_BETA);

    if (tid < 128) { sg[tid] = g1v[tid]; sbe[tid] = b1v[tid]; }
    int w4 = g_mask_w4;
    for (int t = tid; t < KK * 128; t += 256) {
        int m = t / KK, k = t % KK;
        int nr = row0 + m; int id = -1;
        if (nr < n) {
            int off = nr * KK + k;
            if (mask_at(nmask, off, w4)) id = nidx[off];
        }
        sidx[k * 128 + m] = id;
    }
    __syncthreads();

    const int NIT = KK * 2;                  // 54 K=16 chunks
    fill1(sb, sidx, 0, 0, tid); CP_COMMIT();
    fill1(sb, sidx, 1, 1, tid); CP_COMMIT();
    fill1(sb, sidx, 2, 2, tid); CP_COMMIT();

    int mw = wid & 3, nw = wid >> 2;
    int mbase = mw * 32, nbase = nw * 64;
    float acc[2][8][4];
#pragma unroll
    for (int mt = 0; mt < 2; mt++)
#pragma unroll
        for (int nt = 0; nt < 8; nt++)
#pragma unroll
            for (int j = 0; j < 4; j++) acc[mt][nt][j] = 0.f;

    for (int kk = 0; kk < NIT; kk++) {
        int b = kk & 3;
        CP_WAIT_FOR(kk, NIT);
        __syncthreads();
        const uint32_t* A = (const uint32_t*)(dyn + T1_A(b));
        const uint32_t* B = (const uint32_t*)(dyn + T1_B(b));
#pragma unroll
        for (int kt = 0; kt < 2; kt++) {
            int kb = kt * 8;
            uint32_t a[2][4];
#pragma unroll
            for (int mt = 0; mt < 2; mt++) {
                int r = mbase + mt * 16 + g;
                a[mt][0] = A[r * 20 + kb + t4];
                a[mt][1] = A[(r + 8) * 20 + kb + t4];
                a[mt][2] = A[r * 20 + kb + t4 + 4];
                a[mt][3] = A[(r + 8) * 20 + kb + t4 + 4];
            }
#pragma unroll
            for (int nt = 0; nt < 8; nt++) {
                int cn = (nbase + nt * 8 + g) * 20 + kb + t4;
                uint32_t b0 = B[cn], b1 = B[cn + 4];
                mma8(acc[0][nt], a[0], b0, b1);
                mma8(acc[1][nt], a[1], b0, b1);
            }
        }
        if (kk + 3 < NIT) { fill1(sb, sidx, kk + 3, (kk + 3) & 3, tid); CP_COMMIT(); }
    }
    __syncthreads();

    // ---- fused LN(128) + GELU epilogue ----
    float* rs_ = (float*)(dyn + T1_RS);
    float* rq_ = (float*)(dyn + T1_RQ);
#pragma unroll
    for (int mt = 0; mt < 2; mt++)
#pragma unroll
        for (int rr = 0; rr < 2; rr++) {
            float s = 0.f, q = 0.f;
#pragma unroll
            for (int nt = 0; nt < 8; nt++) {
                float v0 = acc[mt][nt][rr * 2], v1 = acc[mt][nt][rr * 2 + 1];
                s += v0 + v1; q += v0 * v0 + v1 * v1;
            }
            s += __shfl_xor_sync(0xffffffffu, s, 1);
            s += __shfl_xor_sync(0xffffffffu, s, 2);
            q += __shfl_xor_sync(0xffffffffu, q, 1);
            q += __shfl_xor_sync(0xffffffffu, q, 2);
            if (t4 == 0) {
                int r = mbase + mt * 16 + rr * 8 + g;
                rs_[r * 2 + nw] = s; rq_[r * 2 + nw] = q;
            }
        }
    __syncthreads();
    float* smu = (float*)(dyn + T1_MU);
    float* ssg = (float*)(dyn + T1_SIG);
    if (tid < 128) {
        float s = rs_[tid * 2] + rs_[tid * 2 + 1];
        float q = rq_[tid * 2] + rq_[tid * 2 + 1];
        float mu = s * (1.0f / 128.0f);
        smu[tid] = mu;
        ssg[tid] = rsqrtf(q * (1.0f / 128.0f) - mu * mu + 1e-6f);
    }
    __syncthreads();
#pragma unroll
    for (int mt = 0; mt < 2; mt++)
#pragma unroll
        for (int rr = 0; rr < 2; rr++) {
            int r = mbase + mt * 16 + rr * 8 + g;
            int nr = row0 + r;
            if (nr >= n) continue;
            float mu = smu[r], rs = ssg[r];
            float* dst = g_h1 + (size_t)nr * 128;
#pragma unroll
            for (int nt = 0; nt < 8; nt++) {
                int c = nbase + nt * 8 + t4 * 2;
                float y0 = to_tf32(gelu_f((acc[mt][nt][rr * 2]     - mu) * rs * sg[c]     + sbe[c]));
                float y1 = to_tf32(gelu_f((acc[mt][nt][rr * 2 + 1] - mu) * rs * sg[c + 1] + sbe[c + 1]));
                *(float2*)(dst + c) = make_float2(y0, y1);
            }
        }
}

// ---------------- conv2: 128x32, K=32 chunks x 108, depth-4 ----------------
// A[s][128][36]f, B[s][32][36]f (stride 36 floats = 144B, conflict-free)
#define T2_A(s)  ((s) * 18432)
#define T2_B(s)  (73728 + (s) * 4608)
#define T2_SIDX  92160
#define T2_G     105984
#define T2_BETA  106112
#define T2_SMEM  106240

__device__ __forceinline__ void fill2(uint32_t sb, const int* sidx, int kk, int st, int tid) {
    int k = kk >> 2, q = kk & 3;
#pragma unroll
    for (int i = 0; i < 4; i++) {            // A: 1024 chunks
        int c = tid + i * 256;
        int row = c >> 3, j = c & 7;
        int id = sidx[k * 128 + row];
        const char* src = (const char*)g_h1 + (size_t)(id < 0 ? 0 : id) * 512 + q * 128 + j * 16;
        cp16(sb + T2_A(st) + row * 144 + j * 16, src, (id < 0) ? 0u : 16u);
    }
    {                                        // B: 256 chunks
        int nr = tid >> 3, j = tid & 7;
        const char* src = (const char*)g_W2t + (size_t)k * 16384 + nr * 512 + q * 128 + j * 16;
        cp16(sb + T2_B(st) + nr * 144 + j * 16, src, 16);
    }
}

__global__ void __launch_bounds__(256, 2)
k_conv2(const float* __restrict__ x, const int* __restrict__ nidx,
        const void* __restrict__ nmask, const float* __restrict__ g2v,
        const float* __restrict__ b2v, float* __restrict__ out, int n) {
    extern __shared__ char dyn[];
    uint32_t sb = smem_u32(dyn);
    int tid = threadIdx.x, wid = tid >> 5, lane = tid & 31;
    int g = lane >> 2, t4 = lane & 3;
    int row0 = blockIdx.x * 128;
    int* sidx = (int*)(dyn + T2_SIDX);
    float* sg  = (float*)(dyn + T2_G);
    float* sbe = (float*)(dyn + T2_BETA);

    if (tid < 32) { sg[tid] = g2v[tid]; sbe[tid] = b2v[tid]; }
    int w4 = g_mask_w4;
    for (int t = tid; t < KK * 128; t += 256) {
        int m = t / KK, k = t % KK;
        int nr = row0 + m; int id = -1;
        if (nr < n) {
            int off = nr * KK + k;
            if (mask_at(nmask, off, w4)) id = nidx[off];
        }
        sidx[k * 128 + m] = id;
    }
    __syncthreads();

    const int NIT = KK * 4;                  // 108 K=32 chunks
    fill2(sb, sidx, 0, 0, tid); CP_COMMIT();
    fill2(sb, sidx, 1, 1, tid); CP_COMMIT();
    fill2(sb, sidx, 2, 2, tid); CP_COMMIT();

    int mw = wid & 3, kh = wid >> 2;         // 4 m-warps x 2 k-halves
    int mbase = mw * 32, kqb = kh * 16;
    float acc[2][4][4];
#pragma unroll
    for (int mt = 0; mt < 2; mt++)
#pragma unroll
        for (int nt = 0; nt < 4; nt++)
#pragma unroll
            for (int j = 0; j < 4; j++) acc[mt][nt][j] = 0.f;

    for (int kk = 0; kk < NIT; kk++) {
        int b = kk & 3;
        CP_WAIT_FOR(kk, NIT);
        __syncthreads();
        const uint32_t* A = (const uint32_t*)(dyn + T2_A(b));
        const uint32_t* B = (const uint32_t*)(dyn + T2_B(b));
#pragma unroll
        for (int kt = 0; kt < 2; kt++) {
            int kb = kqb + kt * 8;
            uint32_t a[2][4];
#pragma unroll
            for (int mt = 0; mt < 2; mt++) {
                int r = mbase + mt * 16 + g;
                a[mt][0] = A[r * 36 + kb + t4];
                a[mt][1] = A[(r + 8) * 36 + kb + t4];
                a[mt][2] = A[r * 36 + kb + t4 + 4];
                a[mt][3] = A[(r + 8) * 36 + kb + t4 + 4];
            }
#pragma unroll
            for (int nt = 0; nt < 4; nt++) {
                int cn = (nt * 8 + g) * 36 + kb + t4;
                uint32_t b0 = B[cn], b1 = B[cn + 4];
                mma8(acc[0][nt], a[0], b0, b1);
                mma8(acc[1][nt], a[1], b0, b1);
            }
        }
        if (kk + 3 < NIT) { fill2(sb, sidx, kk + 3, (kk + 3) & 3, tid); CP_COMMIT(); }
    }
    __syncthreads();

    // ---- k-half reduction via smem (reuse stage0 A region), P[128][34] ----
    float* P = (float*)dyn;
    if (kh == 1) {
#pragma unroll
        for (int mt = 0; mt < 2; mt++)
#pragma unroll
            for (int nt = 0; nt < 4; nt++) {
                int r = mbase + mt * 16 + g, c = nt * 8 + t4 * 2;
                *(float2*)&P[r * 34 + c]       = make_float2(acc[mt][nt][0], acc[mt][nt][1]);
                *(float2*)&P[(r + 8) * 34 + c] = make_float2(acc[mt][nt][2], acc[mt][nt][3]);
            }
    }
    __syncthreads();
    if (kh == 0) {
#pragma unroll
        for (int mt = 0; mt < 2; mt++)
#pragma unroll
            for (int nt = 0; nt < 4; nt++) {
                int r = mbase + mt * 16 + g, c = nt * 8 + t4 * 2;
                float2 p0 = *(float2*)&P[r * 34 + c];
                float2 p1 = *(float2*)&P[(r + 8) * 34 + c];
                acc[mt][nt][0] += p0.x; acc[mt][nt][1] += p0.y;
                acc[mt][nt][2] += p1.x; acc[mt][nt][3] += p1.y;
            }
        // ---- fused LN(32) + residual + GELU ----
#pragma unroll
        for (int mt = 0; mt < 2; mt++)
#pragma unroll
            for (int rr = 0; rr < 2; rr++) {
                float s = 0.f, q = 0.f;
#pragma unroll
                for (int nt = 0; nt < 4; nt++) {
                    float v0 = acc[mt][nt][rr * 2], v1 = acc[mt][nt][rr * 2 + 1];
                    s += v0 + v1; q += v0 * v0 + v1 * v1;
                }
                s += __shfl_xor_sync(0xffffffffu, s, 1);
                s += __shfl_xor_sync(0xffffffffu, s, 2);
                q += __shfl_xor_sync(0xffffffffu, q, 1);
                q += __shfl_xor_sync(0xffffffffu, q, 2);
                float mu = s * (1.0f / 32.0f);
                float rs = rsqrtf(q * (1.0f / 32.0f) - mu * mu + 1e-6f);
                int r = mbase + mt * 16 + rr * 8 + g;
                int nr = row0 + r;
                if (nr >= n) continue;
#pragma unroll
                for (int nt = 0; nt < 4; nt++) {
                    int c = nt * 8 + t4 * 2;
                    float2 xv = *(const float2*)(x + (size_t)nr * 32 + c);
                    float y0 = gelu_f((acc[mt][nt][rr * 2]     - mu) * rs * sg[c]     + sbe[c]     + xv.x);
                    float y1 = gelu_f((acc[mt][nt][rr * 2 + 1] - mu) * rs * sg[c + 1] + sbe[c + 1] + xv.y);
                    *(float2*)(out + (size_t)nr * 32 + c) = make_float2(y0, y1);
                }
            }
    }
}

// ---------------------------------------------------------------------------
extern "C" void kernel_launch(void* const* d_in, const int* in_sizes, int n_in,
                              void* d_out, int out_size) {
    const float* x   = (const float*)d_in[0];
    const int*   nid = (const int*)d_in[1];
    const void*  msk = (const void*)d_in[2];
    const float* Wc  = (const float*)d_in[3];
    const float* g0  = (const float*)d_in[4];
    const float* b0  = (const float*)d_in[5];
    const float* W1  = (const float*)d_in[6];
    const float* g1  = (const float*)d_in[7];
    const float* b1  = (const float*)d_in[8];
    const float* W2  = (const float*)d_in[9];
    const float* g2  = (const float*)d_in[10];
    const float* b2  = (const float*)d_in[11];
    float* out = (float*)d_out;
    int n = in_sizes[0] / 32;

    cudaFuncSetAttribute(k_conv1, cudaFuncAttributeMaxDynamicSharedMemorySize, T1_SMEM);
    cudaFuncSetAttribute(k_conv2, cudaFuncAttributeMaxDynamicSharedMemorySize, T2_SMEM);

    k_prep<<<(KK * 4096 + 255) / 256, 256>>>(W1, W2);
    k_conv0<<<(n + 7) / 8, 256>>>(x, Wc, g0, b0, (const unsigned char*)msk, n);
    int nb = (n + 127) / 128;
    k_conv1<<<nb, 256, T1_SMEM>>>(nid, msk, g1, b1, n);
    k_conv2<<<nb, 256, T2_SMEM>>>(x, nid, msk, g2, b2, out, n);
}